// round 8
// baseline (speedup 1.0000x reference)
#include <cuda_runtime.h>
#include <math.h>

#define DV   128
#define KP   20
#define NOUT 128
#define LNEPS 1e-5f

constexpr int VMAX = 100000;
constexpr int EMAX = 400000;

// ---------------- scratch (device globals; no allocation allowed) ----------------
__device__ float g_npj[VMAX * KP];
__device__ float g_pd[VMAX];
__device__ float g_ps[VMAX];
__device__ float g_hv[VMAX * DV];
__device__ float g_gh[VMAX * 3 * DV];
__device__ float g_gi[VMAX * 3 * DV];
__device__ float g_lmax[VMAX];
__device__ float g_asum[VMAX];
__device__ float g_aexp[EMAX];
__device__ float g_ctx[VMAX * DV];
__device__ float g_kron[VMAX * NOUT];
__device__ float g_gru[VMAX * DV];
__device__ float g_catp[VMAX * DV];

// ---------------- helpers ----------------
__device__ __forceinline__ float warpSum32(float v) {
    #pragma unroll
    for (int m = 16; m > 0; m >>= 1) v += __shfl_xor_sync(0xffffffffu, v, m);
    return v;
}
__device__ __forceinline__ float warpSum16(float v) {
    #pragma unroll
    for (int m = 8; m > 0; m >>= 1) v += __shfl_xor_sync(0xffffffffu, v, m);
    return v;
}

// ---------------- zero init ----------------
__global__ void k_zero(int V) {
    int i = blockIdx.x * blockDim.x + threadIdx.x;
    int n = V * DV;
    if (i < n) { g_ctx[i] = 0.f; g_kron[i] = 0.f; }
    if (i < V) { g_lmax[i] = 0.f; g_asum[i] = 0.f; }
}

// ---------------- per-node precompute: npj (LN+relu over 20), pd, ps ----------------
__global__ __launch_bounds__(256) void k_node_pre(
    const float* __restrict__ nf, const float* __restrict__ Wk1,
    const float* __restrict__ bk1, const float* __restrict__ g1,
    const float* __restrict__ b1, const float* __restrict__ W_edge, int V)
{
    __shared__ __align__(16) float nfs[8][DV];
    int w = threadIdx.x >> 5, lane = threadIdx.x & 31;
    int v = blockIdx.x * 8 + w;
    if (v < V) {
        float4 t = *(const float4*)&nf[(size_t)v * DV + lane * 4];
        *(float4*)&nfs[w][lane * 4] = t;
    }
    __syncwarp();
    if (v >= V) return;

    const float* base;
    int stride;
    if (lane < KP)       { base = Wk1 + lane;     stride = KP; }
    else if (lane == 20) { base = W_edge;         stride = 1;  }
    else if (lane == 21) { base = W_edge + DV;    stride = 1;  }
    else                 { base = W_edge;         stride = 0;  }

    float acc = 0.f;
    #pragma unroll 8
    for (int k = 0; k < DV; k++) acc += nfs[w][k] * base[(size_t)k * stride];

    // LN over lanes 0..19
    float x = (lane < KP) ? acc + bk1[lane] : 0.f;
    float s = warpSum32((lane < KP) ? x : 0.f);
    float mu = s * (1.f / KP);
    float c = (lane < KP) ? (x - mu) : 0.f;
    float q = warpSum32(c * c);
    float rstd = rsqrtf(q * (1.f / KP) + LNEPS);
    if (lane < KP) {
        g_npj[(size_t)v * KP + lane] = fmaxf(c * rstd * g1[lane] + b1[lane], 0.f);
    } else if (lane == 20) {
        g_pd[v] = acc;
    } else if (lane == 21) {
        g_ps[v] = acc;
    }
}

// ---------------- generic tiled SGEMM: C = op(A) @ B + bias ----------------
// A is [M,K] row-major, split at kSplit between A1 (ld=kSplit) and A2 (ld=K-kSplit).
// BT=false: B is [K,N] row-major.  BT=true: B stored [N,K] row-major (B used transposed).
// RA: relu applied to A elements on load.
template<bool BT, bool RA>
__global__ __launch_bounds__(256) void sgemm(
    const float* __restrict__ A1, const float* __restrict__ A2, int kSplit,
    const float* __restrict__ B, const float* __restrict__ bias,
    float* __restrict__ C, int M, int N, int K)
{
    __shared__ __align__(16) float As[16][128];
    __shared__ __align__(16) float Bs[16][128];
    int tid = threadIdx.x;
    int m0 = blockIdx.x * 128;
    int n0 = blockIdx.y * 128;
    int tx = tid & 15;   // col group (8 cols)
    int ty = tid >> 4;   // row group (8 rows)

    float acc[8][8];
    #pragma unroll
    for (int i = 0; i < 8; i++)
        #pragma unroll
        for (int j = 0; j < 8; j++) acc[i][j] = 0.f;

    for (int k0 = 0; k0 < K; k0 += 16) {
        __syncthreads();
        // load A tile (transposed into As[k][m])
        #pragma unroll
        for (int rep = 0; rep < 2; rep++) {
            int id = tid + rep * 256;
            int row = id >> 2;
            int kq = (id & 3) << 2;
            int gr = m0 + row;
            int kk = k0 + kq;
            float4 v = make_float4(0.f, 0.f, 0.f, 0.f);
            if (gr < M) {
                if (kk < kSplit) v = *(const float4*)(A1 + (size_t)gr * kSplit + kk);
                else             v = *(const float4*)(A2 + (size_t)gr * (K - kSplit) + (kk - kSplit));
            }
            if (RA) {
                v.x = fmaxf(v.x, 0.f); v.y = fmaxf(v.y, 0.f);
                v.z = fmaxf(v.z, 0.f); v.w = fmaxf(v.w, 0.f);
            }
            As[kq + 0][row] = v.x; As[kq + 1][row] = v.y;
            As[kq + 2][row] = v.z; As[kq + 3][row] = v.w;
        }
        // load B tile
        if (!BT) {
            #pragma unroll
            for (int rep = 0; rep < 2; rep++) {
                int id = tid + rep * 256;
                int kk = id >> 5;
                int n4 = id & 31;
                float4 v = *(const float4*)(B + (size_t)(k0 + kk) * N + n0 + n4 * 4);
                *(float4*)&Bs[kk][n4 * 4] = v;
            }
        } else {
            #pragma unroll
            for (int rep = 0; rep < 2; rep++) {
                int id = tid + rep * 256;
                int n = id >> 2;
                int kq = (id & 3) << 2;
                float4 v = *(const float4*)(B + (size_t)(n0 + n) * K + k0 + kq);
                Bs[kq + 0][n] = v.x; Bs[kq + 1][n] = v.y;
                Bs[kq + 2][n] = v.z; Bs[kq + 3][n] = v.w;
            }
        }
        __syncthreads();
        #pragma unroll
        for (int k = 0; k < 16; k++) {
            float a[8], b[8];
            *(float4*)&a[0] = *(const float4*)&As[k][ty * 8];
            *(float4*)&a[4] = *(const float4*)&As[k][ty * 8 + 4];
            *(float4*)&b[0] = *(const float4*)&Bs[k][tx * 8];
            *(float4*)&b[4] = *(const float4*)&Bs[k][tx * 8 + 4];
            #pragma unroll
            for (int i = 0; i < 8; i++)
                #pragma unroll
                for (int j = 0; j < 8; j++)
                    acc[i][j] += a[i] * b[j];
        }
    }
    // epilogue
    float bv[8];
    *(float4*)&bv[0] = *(const float4*)&bias[n0 + tx * 8];
    *(float4*)&bv[4] = *(const float4*)&bias[n0 + tx * 8 + 4];
    #pragma unroll
    for (int i = 0; i < 8; i++) {
        int gr = m0 + ty * 8 + i;
        if (gr < M) {
            float4 o0 = make_float4(acc[i][0] + bv[0], acc[i][1] + bv[1],
                                    acc[i][2] + bv[2], acc[i][3] + bv[3]);
            float4 o1 = make_float4(acc[i][4] + bv[4], acc[i][5] + bv[5],
                                    acc[i][6] + bv[6], acc[i][7] + bv[7]);
            *(float4*)(C + (size_t)gr * N + n0 + tx * 8)     = o0;
            *(float4*)(C + (size_t)gr * N + n0 + tx * 8 + 4) = o1;
        }
    }
}

// ---------------- edge attention kernels ----------------
__global__ void k_elogit(const int* __restrict__ src, const int* __restrict__ dst,
                         const float* __restrict__ b_edge, int E)
{
    int e = blockIdx.x * blockDim.x + threadIdx.x;
    if (e >= E) return;
    int dv = dst[e];
    float l = fmaxf(g_pd[dv] + g_ps[src[e]] + b_edge[0], 0.f);
    g_aexp[e] = l;
    atomicMax((int*)&g_lmax[dv], __float_as_int(l));  // valid: l >= 0
}

__global__ void k_eexp(const int* __restrict__ dst, int E)
{
    int e = blockIdx.x * blockDim.x + threadIdx.x;
    if (e >= E) return;
    int dv = dst[e];
    float a = expf(g_aexp[e] - g_lmax[dv]);
    g_aexp[e] = a;
    atomicAdd(&g_asum[dv], a);
}

__global__ __launch_bounds__(256) void k_ectx(const int* __restrict__ src,
                                              const int* __restrict__ dst, int E)
{
    int e = blockIdx.x * 8 + (threadIdx.x >> 5);
    if (e >= E) return;
    int lane = threadIdx.x & 31;
    int s = src[e], dv = dst[e];
    float w = g_aexp[e] / g_asum[dv];
    float4 h = *(const float4*)&g_hv[(size_t)s * DV + lane * 4];
    float* c = &g_ctx[(size_t)dv * DV + lane * 4];
    atomicAdd(c + 0, w * h.x);
    atomicAdd(c + 1, w * h.y);
    atomicAdd(c + 2, w * h.z);
    atomicAdd(c + 3, w * h.w);
}

// ---------------- fused kron edge GEMM + LN + relu + scatter ----------------
// Tile: 64 edges x 128 outs; thread = 4 edges x 8 outs; ot=tid&15 (outs ot*8..+7), et=tid>>4.
__global__ __launch_bounds__(256) void k_kron(
    const int* __restrict__ src, const int* __restrict__ dst,
    const float* __restrict__ Wk2, const float* __restrict__ bk2,
    const float* __restrict__ g2, const float* __restrict__ beta2, int E)
{
    __shared__ float a_s[64][KP];
    __shared__ float b_s[64][KP];
    __shared__ int dst_s[64];
    int tid = threadIdx.x;
    int e0 = blockIdx.x * 64;

    for (int idx = tid; idx < 64 * KP; idx += 256) {
        int e = idx / KP, c = idx % KP;
        int ge = e0 + e;
        float av = 0.f, bv = 0.f;
        if (ge < E) {
            av = g_npj[(size_t)src[ge] * KP + c];
            bv = g_npj[(size_t)dst[ge] * KP + c];
        }
        a_s[e][c] = av;
        b_s[e][c] = bv;
    }
    if (tid < 64) dst_s[tid] = (e0 + tid < E) ? dst[e0 + tid] : 0;
    __syncthreads();

    int ot = tid & 15;
    int et = tid >> 4;
    float acc[4][8];
    #pragma unroll
    for (int e = 0; e < 4; e++)
        #pragma unroll
        for (int c = 0; c < 8; c++) acc[e][c] = 0.f;

    const float4* W4 = (const float4*)Wk2;
    for (int i = 0; i < KP; i++) {
        float a0 = a_s[et * 4 + 0][i];
        float a1 = a_s[et * 4 + 1][i];
        float a2 = a_s[et * 4 + 2][i];
        float a3 = a_s[et * 4 + 3][i];
        #pragma unroll
        for (int j = 0; j < KP; j++) {
            int k = i * KP + j;
            float w[8];
            *(float4*)&w[0] = W4[k * 32 + ot * 2];
            *(float4*)&w[4] = W4[k * 32 + ot * 2 + 1];
            float t[4];
            t[0] = a0 * b_s[et * 4 + 0][j];
            t[1] = a1 * b_s[et * 4 + 1][j];
            t[2] = a2 * b_s[et * 4 + 2][j];
            t[3] = a3 * b_s[et * 4 + 3][j];
            #pragma unroll
            for (int e = 0; e < 4; e++)
                #pragma unroll
                for (int c = 0; c < 8; c++)
                    acc[e][c] += t[e] * w[c];
        }
    }

    // epilogue: bias + LN(128) + relu + atomic scatter
    float bk[8], gg[8], bb[8];
    *(float4*)&bk[0] = *(const float4*)&bk2[ot * 8];
    *(float4*)&bk[4] = *(const float4*)&bk2[ot * 8 + 4];
    *(float4*)&gg[0] = *(const float4*)&g2[ot * 8];
    *(float4*)&gg[4] = *(const float4*)&g2[ot * 8 + 4];
    *(float4*)&bb[0] = *(const float4*)&beta2[ot * 8];
    *(float4*)&bb[4] = *(const float4*)&beta2[ot * 8 + 4];

    #pragma unroll
    for (int e = 0; e < 4; e++) {
        int le = et * 4 + e;
        int ge = e0 + le;
        float pre[8];
        float s = 0.f;
        #pragma unroll
        for (int c = 0; c < 8; c++) { pre[c] = acc[e][c] + bk[c]; s += pre[c]; }
        s = warpSum16(s);
        float mu = s * (1.f / NOUT);
        float q = 0.f;
        #pragma unroll
        for (int c = 0; c < 8; c++) { float d = pre[c] - mu; q += d * d; }
        q = warpSum16(q);
        float rstd = rsqrtf(q * (1.f / NOUT) + LNEPS);
        if (ge < E) {
            float* outp = &g_kron[(size_t)dst_s[le] * NOUT + ot * 8];
            #pragma unroll
            for (int c = 0; c < 8; c++) {
                float y = fmaxf((pre[c] - mu) * rstd * gg[c] + bb[c], 0.f);
                atomicAdd(outp + c, y);
            }
        }
    }
}

// ---------------- GRU combine + relu + LN(128) ----------------
__global__ __launch_bounds__(128) void k_gru(const float* __restrict__ nf,
                                             const float* __restrict__ lng,
                                             const float* __restrict__ lnb, int V)
{
    int v = blockIdx.x;
    int d = threadIdx.x;
    int wid = d >> 5, lane = d & 31;
    const float* gi = g_gi + (size_t)v * 3 * DV;
    const float* gh = g_gh + (size_t)v * 3 * DV;
    float r = 1.f / (1.f + expf(-(gi[d] + gh[d])));
    float z = 1.f / (1.f + expf(-(gi[DV + d] + gh[DV + d])));
    float nn = tanhf(gi[2 * DV + d] + r * gh[2 * DV + d]);
    float h = (1.f - z) * nn + z * nf[(size_t)v * DV + d];
    float x = fmaxf(h, 0.f);

    __shared__ float red[4];
    float s = warpSum32(x);
    if (lane == 0) red[wid] = s;
    __syncthreads();
    float mu = (red[0] + red[1] + red[2] + red[3]) * (1.f / DV);
    __syncthreads();
    float c = x - mu;
    float q = warpSum32(c * c);
    if (lane == 0) red[wid] = q;
    __syncthreads();
    float var = (red[0] + red[1] + red[2] + red[3]) * (1.f / DV);
    g_gru[(size_t)v * DV + d] = c * rsqrtf(var + LNEPS) * lng[d] + lnb[d];
}

// ---------------- final LN + relu ----------------
__global__ __launch_bounds__(128) void k_final(const float* __restrict__ lncg,
                                               const float* __restrict__ lncb,
                                               float* __restrict__ out, int V)
{
    int v = blockIdx.x;
    int d = threadIdx.x;
    int wid = d >> 5, lane = d & 31;
    float x = g_catp[(size_t)v * DV + d];

    __shared__ float red[4];
    float s = warpSum32(x);
    if (lane == 0) red[wid] = s;
    __syncthreads();
    float mu = (red[0] + red[1] + red[2] + red[3]) * (1.f / DV);
    __syncthreads();
    float c = x - mu;
    float q = warpSum32(c * c);
    if (lane == 0) red[wid] = q;
    __syncthreads();
    float var = (red[0] + red[1] + red[2] + red[3]) * (1.f / DV);
    float y = c * rsqrtf(var + LNEPS) * lncg[d] + lncb[d];
    out[(size_t)v * DV + d] = fmaxf(y, 0.f);
}

// ---------------- host ----------------
static inline int cdiv(int a, int b) { return (a + b - 1) / b; }

extern "C" void kernel_launch(void* const* d_in, const int* in_sizes, int n_in,
                              void* d_out, int out_size)
{
    const float* nf     = (const float*)d_in[0];
    const int*   src    = (const int*)d_in[1];
    const int*   dst    = (const int*)d_in[2];
    const float* W_edge = (const float*)d_in[3];
    const float* b_edge = (const float*)d_in[4];
    const float* W_pn   = (const float*)d_in[5];
    const float* b_pn   = (const float*)d_in[6];
    const float* W_ih   = (const float*)d_in[7];
    const float* b_ih   = (const float*)d_in[8];
    const float* W_hh   = (const float*)d_in[9];
    const float* b_hh   = (const float*)d_in[10];
    const float* ln_g   = (const float*)d_in[11];
    const float* ln_b   = (const float*)d_in[12];
    const float* Wk1    = (const float*)d_in[13];
    const float* bk1    = (const float*)d_in[14];
    const float* lnk1_g = (const float*)d_in[15];
    const float* lnk1_b = (const float*)d_in[16];
    const float* Wk2    = (const float*)d_in[17];
    const float* bk2    = (const float*)d_in[18];
    const float* lnk2_g = (const float*)d_in[19];
    const float* lnk2_b = (const float*)d_in[20];
    const float* Wc     = (const float*)d_in[21];
    const float* bc     = (const float*)d_in[22];
    const float* lnc_g  = (const float*)d_in[23];
    const float* lnc_b  = (const float*)d_in[24];
    float* out = (float*)d_out;

    int V = in_sizes[0] / DV;
    int E = in_sizes[1];

    float *p_hv, *p_gh, *p_gi, *p_ctx, *p_gru, *p_kron, *p_catp;
    cudaGetSymbolAddress((void**)&p_hv,   g_hv);
    cudaGetSymbolAddress((void**)&p_gh,   g_gh);
    cudaGetSymbolAddress((void**)&p_gi,   g_gi);
    cudaGetSymbolAddress((void**)&p_ctx,  g_ctx);
    cudaGetSymbolAddress((void**)&p_gru,  g_gru);
    cudaGetSymbolAddress((void**)&p_kron, g_kron);
    cudaGetSymbolAddress((void**)&p_catp, g_catp);

    k_zero<<<cdiv(V * DV, 256), 256>>>(V);
    k_node_pre<<<cdiv(V, 8), 256>>>(nf, Wk1, bk1, lnk1_g, lnk1_b, W_edge, V);

    // hv = nf @ W_pn + b_pn
    sgemm<false, false><<<dim3(cdiv(V, 128), 1), 256>>>(nf, nf, DV, W_pn, b_pn, p_hv, V, DV, DV);
    // gh = nf @ W_hh^T + b_hh
    sgemm<true, false><<<dim3(cdiv(V, 128), 3), 256>>>(nf, nf, DV, W_hh, b_hh, p_gh, V, 3 * DV, DV);

    k_elogit<<<cdiv(E, 256), 256>>>(src, dst, b_edge, E);
    k_eexp<<<cdiv(E, 256), 256>>>(dst, E);
    k_ectx<<<cdiv(E, 8), 256>>>(src, dst, E);

    k_kron<<<cdiv(E, 64), 256>>>(src, dst, Wk2, bk2, lnk2_g, lnk2_b, E);

    // gi = relu(context) @ W_ih^T + b_ih
    sgemm<true, true><<<dim3(cdiv(V, 128), 3), 256>>>(p_ctx, p_ctx, DV, W_ih, b_ih, p_gi, V, 3 * DV, DV);

    k_gru<<<V, 128>>>(nf, ln_g, ln_b, V);

    // cat_pre = [gru, kron] @ Wc + bc
    sgemm<false, false><<<dim3(cdiv(V, 128), 1), 256>>>(p_gru, p_kron, DV, Wc, bc, p_catp, V, DV, 2 * DV);

    k_final<<<V, 128>>>(lnc_g, lnc_b, out, V);
}